// round 1
// baseline (speedup 1.0000x reference)
#include <cuda_runtime.h>

#define D   128   // LATDIM
#define A   64    // ANCHOR_SET_NUM
#define TN  64    // n-tile for main kernel

// Scratch (allocation-free rule: __device__ globals)
__device__ float g_V[A * D];        // (1/A) * set_emb @ W1^T   [A][D]
__device__ float g_C[10000 * D];    // per-residue constant     [T][D] (T <= N)

// ---------------------------------------------------------------------------
// K1: V[a][o] = (1/A) * sum_k embeds[anchor[a]][k] * W[o][k]
// 64 blocks (one per anchor), 128 threads. Warp-cooperative dot so W reads
// are coalesced (lanes split k).
// ---------------------------------------------------------------------------
__global__ __launch_bounds__(128) void k_anchor(const float* __restrict__ embeds,
                                                const float* __restrict__ W,
                                                const int*   __restrict__ anchor) {
    __shared__ float se[D];
    const int a    = blockIdx.x;
    const int tid  = threadIdx.x;
    const int lane = tid & 31;
    const int warp = tid >> 5;

    const int row = anchor[a];
    se[tid] = embeds[(size_t)row * D + tid];
    __syncthreads();

    // each warp computes 32 consecutive o's
    #pragma unroll 4
    for (int oo = 0; oo < 32; oo++) {
        const int o = warp * 32 + oo;
        const float* w = W + (size_t)o * (2 * D);   // W1 row
        float acc = 0.f;
        #pragma unroll
        for (int kk = 0; kk < D / 32; kk++) {
            const int k = kk * 32 + lane;
            acc += se[k] * w[k];
        }
        #pragma unroll
        for (int off = 16; off; off >>= 1)
            acc += __shfl_xor_sync(0xffffffffu, acc, off);
        if (lane == 0) g_V[a * D + o] = acc * (1.0f / A);
    }
}

// ---------------------------------------------------------------------------
// K2: C[t][o] = (1/A) * sum_k E2[t][k] * W[o][D+k] + b[o]
//     E2[t]   = sum_{a<A} embeds[(g*t + a) mod N]
// T = N/gcd(A,N) blocks, 128 threads.
// ---------------------------------------------------------------------------
__global__ __launch_bounds__(128) void k_const(const float* __restrict__ embeds,
                                               const float* __restrict__ W,
                                               const float* __restrict__ b,
                                               int N, int g) {
    __shared__ float e2[D];
    const int t    = blockIdx.x;
    const int tid  = threadIdx.x;
    const int lane = tid & 31;
    const int warp = tid >> 5;

    // window sum of A consecutive rows (with wrap), component `tid`
    const int s = g * t;
    float sum = 0.f;
    #pragma unroll 8
    for (int a = 0; a < A; a++) {
        int r = s + a;
        if (r >= N) r -= N;
        sum += embeds[(size_t)r * D + tid];
    }
    e2[tid] = sum;
    __syncthreads();

    #pragma unroll 4
    for (int oo = 0; oo < 32; oo++) {
        const int o = warp * 32 + oo;
        const float* w = W + (size_t)o * (2 * D) + D;  // W2 row
        float acc = 0.f;
        #pragma unroll
        for (int kk = 0; kk < D / 32; kk++) {
            const int k = kk * 32 + lane;
            acc += e2[k] * w[k];
        }
        #pragma unroll
        for (int off = 16; off; off >>= 1)
            acc += __shfl_xor_sync(0xffffffffu, acc, off);
        if (lane == 0) g_C[t * D + o] = acc * (1.0f / A) + b[o];
    }
}

// ---------------------------------------------------------------------------
// K3: out[n][o] = sum_a sd[a][n] * sv[a][o]  +  C[(step*n) mod T][o]
// Block: 256 threads, tile 64 n x 128 o. Each thread: 8 n x 4 o register tile.
// smem: V (32KB) + dists tile (16KB) = 48KB.
// ---------------------------------------------------------------------------
__global__ __launch_bounds__(256) void k_main(const float* __restrict__ dists,
                                              float* __restrict__ out,
                                              int N, int T, int step) {
    __shared__ float sv[A][D];    // 32768 B
    __shared__ float sd[A][TN];   // 16384 B

    const int n0  = blockIdx.x * TN;
    const int tid = threadIdx.x;

    // stage V
    #pragma unroll
    for (int i = tid; i < A * D / 4; i += 256)
        ((float4*)sv)[i] = ((const float4*)g_V)[i];

    // stage dists tile: sd[a][j] = dists[a*N + n0 + j] (zero-padded)
    #pragma unroll
    for (int i = tid; i < A * TN / 4; i += 256) {
        const int a  = i / (TN / 4);
        const int j4 = (i % (TN / 4)) * 4;
        const int n  = n0 + j4;
        const float* src = dists + (size_t)a * N + n;
        float4 v;
        if (n + 3 < N) {
            v = *(const float4*)src;
        } else {
            v.x = (n + 0 < N) ? src[0] : 0.f;
            v.y = (n + 1 < N) ? src[1] : 0.f;
            v.z = (n + 2 < N) ? src[2] : 0.f;
            v.w = (n + 3 < N) ? src[3] : 0.f;
        }
        ((float4*)sd)[i] = v;
    }
    __syncthreads();

    const int ob = (tid & 31) * 4;   // o base: lanes cover all 128 o (coalesced)
    const int nb = (tid >> 5) * 8;   // n base: per-warp constant (smem broadcast)

    float acc[8][4];
    #pragma unroll
    for (int i = 0; i < 8; i++)
        #pragma unroll
        for (int j = 0; j < 4; j++) acc[i][j] = 0.f;

    #pragma unroll 8
    for (int a = 0; a < A; a++) {
        const float4 v  = *(const float4*)&sv[a][ob];
        const float4 d0 = *(const float4*)&sd[a][nb];
        const float4 d1 = *(const float4*)&sd[a][nb + 4];
        const float dv[8] = {d0.x, d0.y, d0.z, d0.w, d1.x, d1.y, d1.z, d1.w};
        #pragma unroll
        for (int i = 0; i < 8; i++) {
            acc[i][0] += dv[i] * v.x;
            acc[i][1] += dv[i] * v.y;
            acc[i][2] += dv[i] * v.z;
            acc[i][3] += dv[i] * v.w;
        }
    }

    // epilogue: add C[t(n)] and store
    #pragma unroll
    for (int i = 0; i < 8; i++) {
        const int n = n0 + nb + i;
        if (n >= N) break;
        const int t = (int)(((long long)step * n) % T);
        const float4 c = *(const float4*)&g_C[t * D + ob];
        float4 r;
        r.x = acc[i][0] + c.x;
        r.y = acc[i][1] + c.y;
        r.z = acc[i][2] + c.z;
        r.w = acc[i][3] + c.w;
        *(float4*)&out[(size_t)n * D + ob] = r;
    }
}

// ---------------------------------------------------------------------------
extern "C" void kernel_launch(void* const* d_in, const int* in_sizes, int n_in,
                              void* d_out, int out_size) {
    const float* embeds = (const float*)d_in[0];   // [N, 128]
    const float* dists  = (const float*)d_in[1];   // [64, N]
    const float* W      = (const float*)d_in[2];   // [128, 256]
    const float* b      = (const float*)d_in[3];   // [128]
    const int*   anchor = (const int*)  d_in[4];   // [64] int32
    float* out = (float*)d_out;

    const int N = in_sizes[0] / D;                 // 10000

    // g = gcd(A, N); T = N/g distinct self-feature windows; t(n) = (A/g * n) mod T
    int g = A, y = N;
    while (y) { int r = g % y; g = y; y = r; }
    const int T    = N / g;
    const int step = A / g;

    k_anchor<<<A, 128>>>(embeds, W, anchor);
    k_const<<<T, 128>>>(embeds, W, b, N, g);
    k_main<<<(N + TN - 1) / TN, 256>>>(dists, out, N, T, step);
}